// round 1
// baseline (speedup 1.0000x reference)
#include <cuda_runtime.h>
#include <cuda_bf16.h>
#include <math.h>

#define Bz 2
#define Sz 2048
#define Dm 1024
#define Hh 16
#define HD 64
#define NT (Bz*Sz)          // 4096 tokens

// ---------------- scratch (device globals; zero-init at load) ----------------
__device__ float g_featA[NT * 512];
__device__ float g_featF[NT * 1024];
__device__ float g_hidden[NT * 1024];
__device__ float g_q[NT * 1024];
__device__ float g_k[NT * 1024];
__device__ float g_v[NT * 1024];
__device__ float g_attn[NT * 1024];
__device__ float g_bias[Bz * Sz * Sz];     // 33.5 MB, fits L2
__device__ float g_zero_bias[1024];        // stays zero

// ---------------- featurize: per-token feature construction ----------------
__global__ void featurize_kernel(const int* __restrict__ enc,
                                 const float* __restrict__ emb1_w, const float* __restrict__ emb1_b,
                                 const float* __restrict__ log_w,  const float* __restrict__ log_b,
                                 const float* __restrict__ prime_w,const float* __restrict__ prime_b,
                                 const float* __restrict__ div_w,  const float* __restrict__ div_b,
                                 const float* __restrict__ bit_w,  const float* __restrict__ bit_b,
                                 float* __restrict__ featA, float* __restrict__ featF)
{
    int t = blockIdx.x;                 // token id
    int tid = threadIdx.x;
    int e = enc[t];
    float ef = (float)e;
    float norm = ef / 2147483647.0f;
    float lg = logf(ef + 1.0f);

    __shared__ float pflag[10];
    __shared__ float dfrac[20];
    __shared__ float bflag[32];
    if (tid < 10) {
        const int primes[10] = {2,3,5,7,11,13,17,19,23,29};
        pflag[tid] = (e % primes[tid] == 0) ? 1.0f : 0.0f;
    } else if (tid < 30) {
        int tv = (tid - 10) + 2;
        dfrac[tid-10] = (float)(e % tv) / (float)tv;
    } else if (tid < 62) {
        int s = tid - 30;
        bflag[s] = (float)((e >> s) & 1);
    }
    __syncthreads();

    // featA: relu(norm * emb1_w + emb1_b)  (512)
    for (int c = tid; c < 512; c += 256) {
        float vv = fmaf(norm, emb1_w[c], emb1_b[c]);
        featA[t*512 + c] = fmaxf(vv, 0.0f);
    }
    // featF: [logf(256) | pf(256) | df(256) | bf(256)]
    for (int c = tid; c < 1024; c += 256) {
        int cc = c & 255;
        float vv;
        if (c < 256) {
            vv = fmaf(lg, log_w[cc], log_b[cc]);
        } else if (c < 512) {
            vv = prime_b[cc];
            #pragma unroll
            for (int p = 0; p < 10; p++) vv = fmaf(pflag[p], prime_w[p*256 + cc], vv);
        } else if (c < 768) {
            vv = div_b[cc];
            #pragma unroll
            for (int p = 0; p < 20; p++) vv = fmaf(dfrac[p], div_w[p*256 + cc], vv);
        } else {
            vv = bit_b[cc];
            #pragma unroll
            for (int p = 0; p < 32; p++) vv = fmaf(bflag[p], bit_w[p*256 + cc], vv);
        }
        featF[t*1024 + c] = vv;
    }
}

// ---------------- pairwise gcd-approx bias precompute ----------------
__global__ void bias_kernel(const int* __restrict__ enc, float* __restrict__ biasOut)
{
    int idx = blockIdx.x * blockDim.x + threadIdx.x;   // over Bz*Sz*Sz = 8.4M
    if (idx >= Bz*Sz*Sz) return;
    int j = idx & (Sz - 1);
    int r = idx >> 11;          // / Sz
    int i = r & (Sz - 1);
    int b = r >> 11;
    int ei = enc[b*Sz + i];
    int ej = enc[b*Sz + j];
    float bias;
    if (i == j) {
        bias = 0.0f;
    } else {
        unsigned m1 = (unsigned)ei % (unsigned)(ej + 1);
        unsigned m2 = (unsigned)ej % (unsigned)(ei + 1);
        unsigned g  = m1 < m2 ? m1 : m2;
        int mx = ei > ej ? ei : ej;
        bias = (float)g / (float)(mx + 1);
    }
    biasOut[idx] = bias;
}

// ---------------- SGEMM core: 128x128x8 tile, 8x8 microtile, 256 threads ----------------
__device__ __forceinline__ void gemm_loop(const float* __restrict__ A, const float* __restrict__ B,
                                          int K, int block_row, int block_col, int tid,
                                          float (&acc)[8][8],
                                          float (*As)[128], float (*Bs)[128])
{
    const int N = 1024;
    int a_row = tid >> 1;
    int a_col = (tid & 1) * 4;
    int b_row = tid >> 5;
    int b_col = (tid & 31) * 4;
    int tx = tid & 15, ty = tid >> 4;

    for (int k0 = 0; k0 < K; k0 += 8) {
        float4 a4 = *(const float4*)(A + (block_row + a_row) * K + k0 + a_col);
        As[a_col+0][a_row] = a4.x;
        As[a_col+1][a_row] = a4.y;
        As[a_col+2][a_row] = a4.z;
        As[a_col+3][a_row] = a4.w;
        *(float4*)(&Bs[b_row][b_col]) = *(const float4*)(B + (k0 + b_row) * N + block_col + b_col);
        __syncthreads();
        #pragma unroll
        for (int kk = 0; kk < 8; kk++) {
            float ar[8], br[8];
            #pragma unroll
            for (int i = 0; i < 8; i++) ar[i] = As[kk][ty*8 + i];
            #pragma unroll
            for (int j = 0; j < 8; j++) br[j] = Bs[kk][tx*8 + j];
            #pragma unroll
            for (int i = 0; i < 8; i++)
                #pragma unroll
                for (int j = 0; j < 8; j++)
                    acc[i][j] = fmaf(ar[i], br[j], acc[i][j]);
        }
        __syncthreads();
    }
}

__device__ __forceinline__ void gemm_epilogue(float* __restrict__ C,
                                              const float* __restrict__ b1,
                                              const float* __restrict__ b2,
                                              int block_row, int block_col, int tid,
                                              float (&acc)[8][8])
{
    const int N = 1024;
    int tx = tid & 15, ty = tid >> 4;
    #pragma unroll
    for (int i = 0; i < 8; i++) {
        int row = block_row + ty*8 + i;
        #pragma unroll
        for (int j = 0; j < 8; j += 4) {
            int col = block_col + tx*8 + j;
            float4 o;
            o.x = acc[i][j+0] + b1[col+0] + b2[col+0];
            o.y = acc[i][j+1] + b1[col+1] + b2[col+1];
            o.z = acc[i][j+2] + b1[col+2] + b2[col+2];
            o.w = acc[i][j+3] + b1[col+3] + b2[col+3];
            *(float4*)(C + row * N + col) = o;
        }
    }
}

// hidden = featA @ emb2_w + featF @ fus_w + emb2_b + fus_b
__global__ void __launch_bounds__(256) gemm_hidden_kernel(
        const float* __restrict__ A1, const float* __restrict__ B1,
        const float* __restrict__ A2, const float* __restrict__ B2,
        const float* __restrict__ bias1, const float* __restrict__ bias2,
        float* __restrict__ C)
{
    __shared__ float As[8][128];
    __shared__ float Bs[8][128];
    int tid = threadIdx.x;
    int block_row = blockIdx.y * 128;
    int block_col = blockIdx.x * 128;
    float acc[8][8];
    #pragma unroll
    for (int i = 0; i < 8; i++)
        #pragma unroll
        for (int j = 0; j < 8; j++) acc[i][j] = 0.0f;
    gemm_loop(A1, B1, 512,  block_row, block_col, tid, acc, As, Bs);
    gemm_loop(A2, B2, 1024, block_row, block_col, tid, acc, As, Bs);
    gemm_epilogue(C, bias1, bias2, block_row, block_col, tid, acc);
}

// q/k/v = hidden @ {q,k,v}_w + bias ; blockIdx.z selects target
__global__ void __launch_bounds__(256) gemm_qkv_kernel(
        const float* __restrict__ Hd,
        const float* __restrict__ q_w, const float* __restrict__ q_b,
        const float* __restrict__ k_w, const float* __restrict__ k_b,
        const float* __restrict__ v_w, const float* __restrict__ v_b,
        const float* __restrict__ zero_b,
        float* __restrict__ Qo, float* __restrict__ Ko, float* __restrict__ Vo)
{
    __shared__ float As[8][128];
    __shared__ float Bs[8][128];
    const float* W;
    const float* bb;
    float* C;
    if (blockIdx.z == 0)      { W = q_w; bb = q_b; C = Qo; }
    else if (blockIdx.z == 1) { W = k_w; bb = k_b; C = Ko; }
    else                      { W = v_w; bb = v_b; C = Vo; }
    int tid = threadIdx.x;
    int block_row = blockIdx.y * 128;
    int block_col = blockIdx.x * 128;
    float acc[8][8];
    #pragma unroll
    for (int i = 0; i < 8; i++)
        #pragma unroll
        for (int j = 0; j < 8; j++) acc[i][j] = 0.0f;
    gemm_loop(Hd, W, 1024, block_row, block_col, tid, acc, As, Bs);
    gemm_epilogue(C, bb, zero_b, block_row, block_col, tid, acc);
}

// out = attn_out @ o_w + o_b
__global__ void __launch_bounds__(256) gemm_single_kernel(
        const float* __restrict__ A, const float* __restrict__ W,
        const float* __restrict__ bias, const float* __restrict__ zero_b,
        float* __restrict__ C)
{
    __shared__ float As[8][128];
    __shared__ float Bs[8][128];
    int tid = threadIdx.x;
    int block_row = blockIdx.y * 128;
    int block_col = blockIdx.x * 128;
    float acc[8][8];
    #pragma unroll
    for (int i = 0; i < 8; i++)
        #pragma unroll
        for (int j = 0; j < 8; j++) acc[i][j] = 0.0f;
    gemm_loop(A, W, 1024, block_row, block_col, tid, acc, As, Bs);
    gemm_epilogue(C, bias, zero_b, block_row, block_col, tid, acc);
}

// ---------------- flash attention: 64 queries x 64 keys tiles ----------------
#define QPAD 68
#define ATTN_SMEM (4 * 64 * QPAD * 4)

__global__ void __launch_bounds__(256) attention_kernel(
        const float* __restrict__ q, const float* __restrict__ k, const float* __restrict__ v,
        const float* __restrict__ biasG, const float* __restrict__ arith_bias,
        const float* __restrict__ gcd_w, float* __restrict__ o)
{
    extern __shared__ float sm[];
    float* sQ = sm;
    float* sK = sm + 64 * QPAD;
    float* sV = sm + 2 * 64 * QPAD;
    float* sP = sm + 3 * 64 * QPAD;

    int bh = blockIdx.y;
    int b = bh >> 4;
    int h = bh & 15;
    int i0 = blockIdx.x * 64;
    int tid = threadIdx.x;
    int tx = tid & 15, ty = tid >> 4;
    float gw = gcd_w[0];
    float ab = arith_bias[h];
    const float scale = 0.125f;   // 1/sqrt(64)
    const float* biasB = biasG + b * (Sz * Sz);

    // load Q tile [64][64]
    for (int f = tid; f < 64 * 16; f += 256) {
        int r = f >> 4, c4 = (f & 15) * 4;
        *(float4*)(&sQ[r * QPAD + c4]) =
            *(const float4*)(q + ((b*Sz + i0 + r) * Dm) + h*HD + c4);
    }

    float m_i[4], l_i[4], acc[4][4];
    #pragma unroll
    for (int r = 0; r < 4; r++) {
        m_i[r] = -1e30f; l_i[r] = 0.0f;
        #pragma unroll
        for (int c = 0; c < 4; c++) acc[r][c] = 0.0f;
    }

    for (int j0 = 0; j0 < Sz; j0 += 64) {
        __syncthreads();   // protect K/V/P overwrite vs previous iteration readers
        for (int f = tid; f < 64 * 16; f += 256) {
            int r = f >> 4, c4 = (f & 15) * 4;
            int base = ((b*Sz + j0 + r) * Dm) + h*HD + c4;
            *(float4*)(&sK[r * QPAD + c4]) = *(const float4*)(k + base);
            *(float4*)(&sV[r * QPAD + c4]) = *(const float4*)(v + base);
        }
        __syncthreads();

        // scores 4x4 per thread
        float s[4][4];
        #pragma unroll
        for (int r = 0; r < 4; r++)
            #pragma unroll
            for (int c = 0; c < 4; c++) s[r][c] = 0.0f;
        #pragma unroll 4
        for (int d = 0; d < 64; d++) {
            float a_[4], b_[4];
            #pragma unroll
            for (int r = 0; r < 4; r++) a_[r] = sQ[(ty*4 + r) * QPAD + d];
            #pragma unroll
            for (int c = 0; c < 4; c++) b_[c] = sK[(tx*4 + c) * QPAD + d];
            #pragma unroll
            for (int r = 0; r < 4; r++)
                #pragma unroll
                for (int c = 0; c < 4; c++)
                    s[r][c] = fmaf(a_[r], b_[c], s[r][c]);
        }

        // scale + bias + online softmax update
        #pragma unroll
        for (int r = 0; r < 4; r++) {
            int gi = i0 + ty*4 + r;
            float4 bb = *(const float4*)(biasB + gi * Sz + j0 + tx*4);
            s[r][0] = fmaf(bb.x, gw, s[r][0] * scale + ab);
            s[r][1] = fmaf(bb.y, gw, s[r][1] * scale + ab);
            s[r][2] = fmaf(bb.z, gw, s[r][2] * scale + ab);
            s[r][3] = fmaf(bb.w, gw, s[r][3] * scale + ab);

            float pm = fmaxf(fmaxf(s[r][0], s[r][1]), fmaxf(s[r][2], s[r][3]));
            #pragma unroll
            for (int ofs = 8; ofs >= 1; ofs >>= 1)
                pm = fmaxf(pm, __shfl_xor_sync(0xffffffffu, pm, ofs));
            float mnew = fmaxf(m_i[r], pm);
            float corr = __expf(m_i[r] - mnew);
            float psum = 0.0f;
            #pragma unroll
            for (int c = 0; c < 4; c++) {
                s[r][c] = __expf(s[r][c] - mnew);
                psum += s[r][c];
            }
            #pragma unroll
            for (int ofs = 8; ofs >= 1; ofs >>= 1)
                psum += __shfl_xor_sync(0xffffffffu, psum, ofs);
            l_i[r] = l_i[r] * corr + psum;
            m_i[r] = mnew;
            #pragma unroll
            for (int c = 0; c < 4; c++) acc[r][c] *= corr;
            *(float4*)(&sP[(ty*4 + r) * QPAD + tx*4]) =
                make_float4(s[r][0], s[r][1], s[r][2], s[r][3]);
        }
        __syncthreads();

        // acc += P @ V
        #pragma unroll 4
        for (int jj = 0; jj < 64; jj++) {
            float pv[4], vv[4];
            #pragma unroll
            for (int r = 0; r < 4; r++) pv[r] = sP[(ty*4 + r) * QPAD + jj];
            #pragma unroll
            for (int c = 0; c < 4; c++) vv[c] = sV[jj * QPAD + tx*4 + c];
            #pragma unroll
            for (int r = 0; r < 4; r++)
                #pragma unroll
                for (int c = 0; c < 4; c++)
                    acc[r][c] = fmaf(pv[r], vv[c], acc[r][c]);
        }
    }

    // epilogue: normalize, write (b, i, h, d)
    #pragma unroll
    for (int r = 0; r < 4; r++) {
        float inv = 1.0f / l_i[r];
        int gi = i0 + ty*4 + r;
        float4 ov = make_float4(acc[r][0]*inv, acc[r][1]*inv, acc[r][2]*inv, acc[r][3]*inv);
        *(float4*)(o + ((b*Sz + gi) * Dm) + h*HD + tx*4) = ov;
    }
}

// ---------------- launch ----------------
extern "C" void kernel_launch(void* const* d_in, const int* in_sizes, int n_in,
                              void* d_out, int out_size)
{
    // encodings is the unique input with 4096 elements (B*S); its position
    // disambiguates reference-signature order vs setup_inputs dict order.
    int enc_idx = -1;
    for (int i = 0; i < n_in; i++) if (in_sizes[i] == 4096) { enc_idx = i; break; }
    if (enc_idx < 0) enc_idx = 0;

    const float* P[24];
    int p = 0;
    for (int i = 0; i < n_in && p < 24; i++) {
        if (i == enc_idx) continue;
        P[p++] = (const float*)d_in[i];
    }
    const int* enc = (const int*)d_in[enc_idx];
    const float *q_w = P[0],  *q_b = P[1],  *k_w = P[2],  *k_b = P[3];
    const float *v_w = P[4],  *v_b = P[5],  *o_w = P[6],  *o_b = P[7];
    const float *emb1_w = P[8],  *emb1_b = P[9],  *emb2_w = P[10], *emb2_b = P[11];
    const float *log_w = P[12],  *log_b = P[13],  *prime_w = P[14], *prime_b = P[15];
    const float *div_w = P[16],  *div_b = P[17],  *bit_w = P[18],  *bit_b = P[19];
    const float *fus_w = P[20],  *fus_b = P[21],  *arith = P[22],  *gcdw = P[23];
    float* out = (float*)d_out;

    float *featA, *featF, *hidden, *Q, *K, *V, *attn, *biasM, *zb;
    cudaGetSymbolAddress((void**)&featA,  g_featA);
    cudaGetSymbolAddress((void**)&featF,  g_featF);
    cudaGetSymbolAddress((void**)&hidden, g_hidden);
    cudaGetSymbolAddress((void**)&Q,      g_q);
    cudaGetSymbolAddress((void**)&K,      g_k);
    cudaGetSymbolAddress((void**)&V,      g_v);
    cudaGetSymbolAddress((void**)&attn,   g_attn);
    cudaGetSymbolAddress((void**)&biasM,  g_bias);
    cudaGetSymbolAddress((void**)&zb,     g_zero_bias);

    featurize_kernel<<<NT, 256>>>(enc, emb1_w, emb1_b, log_w, log_b,
                                  prime_w, prime_b, div_w, div_b, bit_w, bit_b,
                                  featA, featF);
    bias_kernel<<<(Bz*Sz*Sz + 255) / 256, 256>>>(enc, biasM);
    gemm_hidden_kernel<<<dim3(8, 32), 256>>>(featA, emb2_w, featF, fus_w,
                                             emb2_b, fus_b, hidden);
    gemm_qkv_kernel<<<dim3(8, 32, 3), 256>>>(hidden, q_w, q_b, k_w, k_b, v_w, v_b,
                                             zb, Q, K, V);
    cudaFuncSetAttribute(attention_kernel,
                         cudaFuncAttributeMaxDynamicSharedMemorySize, ATTN_SMEM);
    attention_kernel<<<dim3(Sz/64, Bz*Hh), 256, ATTN_SMEM>>>(Q, K, V, biasM,
                                                             arith, gcdw, attn);
    gemm_single_kernel<<<dim3(8, 32), 256>>>(attn, o_w, o_b, zb, out);
}

// round 2
// speedup vs baseline: 1.4273x; 1.4273x over previous
#include <cuda_runtime.h>
#include <cuda_bf16.h>
#include <math.h>

#define Bz 2
#define Sz 2048
#define Dm 1024
#define Hh 16
#define HD 64
#define NT (Bz*Sz)          // 4096 tokens

// ---------------- scratch (device globals) ----------------
__device__ float g_featA[NT * 512];
__device__ float g_featF[NT * 1024];
__device__ float g_hidden[NT * 1024];
__device__ float g_q[NT * 1024];
__device__ float g_k[NT * 1024];
__device__ float g_v[NT * 1024];
__device__ float g_attn[NT * 1024];
__device__ float g_bias[Bz * Sz * Sz];     // 33.5 MB
__device__ float g_zero_bias[1024];        // stays zero
// tf32-rounded weight copies
__device__ float g_qw_t[1024*1024];
__device__ float g_kw_t[1024*1024];
__device__ float g_vw_t[1024*1024];
__device__ float g_ow_t[1024*1024];
__device__ float g_emb2_t[512*1024];
__device__ float g_fus_t[1024*1024];

// ---------------- tf32 rounding ----------------
__device__ __forceinline__ float tf32r(float x) {
    unsigned r;
    asm("cvt.rna.tf32.f32 %0, %1;" : "=r"(r) : "f"(x));
    return __uint_as_float(r);
}

__global__ void convert_tf32_kernel(const float* __restrict__ s, float* __restrict__ d, int n) {
    int i = blockIdx.x * 256 + threadIdx.x;
    if (i < n) d[i] = tf32r(s[i]);
}

// ---------------- featurize: per-token feature construction ----------------
__global__ void featurize_kernel(const int* __restrict__ enc,
                                 const float* __restrict__ emb1_w, const float* __restrict__ emb1_b,
                                 const float* __restrict__ log_w,  const float* __restrict__ log_b,
                                 const float* __restrict__ prime_w,const float* __restrict__ prime_b,
                                 const float* __restrict__ div_w,  const float* __restrict__ div_b,
                                 const float* __restrict__ bit_w,  const float* __restrict__ bit_b,
                                 float* __restrict__ featA, float* __restrict__ featF)
{
    int t = blockIdx.x;
    int tid = threadIdx.x;
    int e = enc[t];
    float ef = (float)e;
    float norm = ef / 2147483647.0f;
    float lg = logf(ef + 1.0f);

    __shared__ float pflag[10];
    __shared__ float dfrac[20];
    __shared__ float bflag[32];
    if (tid < 10) {
        const int primes[10] = {2,3,5,7,11,13,17,19,23,29};
        pflag[tid] = (e % primes[tid] == 0) ? 1.0f : 0.0f;
    } else if (tid < 30) {
        int tv = (tid - 10) + 2;
        dfrac[tid-10] = (float)(e % tv) / (float)tv;
    } else if (tid < 62) {
        int s = tid - 30;
        bflag[s] = (float)((e >> s) & 1);
    }
    __syncthreads();

    for (int c = tid; c < 512; c += 256) {
        float vv = fmaf(norm, emb1_w[c], emb1_b[c]);
        featA[t*512 + c] = tf32r(fmaxf(vv, 0.0f));
    }
    for (int c = tid; c < 1024; c += 256) {
        int cc = c & 255;
        float vv;
        if (c < 256) {
            vv = fmaf(lg, log_w[cc], log_b[cc]);
        } else if (c < 512) {
            vv = prime_b[cc];
            #pragma unroll
            for (int p = 0; p < 10; p++) vv = fmaf(pflag[p], prime_w[p*256 + cc], vv);
        } else if (c < 768) {
            vv = div_b[cc];
            #pragma unroll
            for (int p = 0; p < 20; p++) vv = fmaf(dfrac[p], div_w[p*256 + cc], vv);
        } else {
            vv = bit_b[cc];
            #pragma unroll
            for (int p = 0; p < 32; p++) vv = fmaf(bflag[p], bit_w[p*256 + cc], vv);
        }
        featF[t*1024 + c] = tf32r(vv);
    }
}

// ---------------- pairwise gcd-approx bias precompute ----------------
__global__ void bias_kernel(const int* __restrict__ enc, float* __restrict__ biasOut)
{
    int idx = blockIdx.x * blockDim.x + threadIdx.x;
    if (idx >= Bz*Sz*Sz) return;
    int j = idx & (Sz - 1);
    int r = idx >> 11;
    int i = r & (Sz - 1);
    int b = r >> 11;
    int ei = enc[b*Sz + i];
    int ej = enc[b*Sz + j];
    float bias;
    if (i == j) {
        bias = 0.0f;
    } else {
        unsigned m1 = (unsigned)ei % (unsigned)(ej + 1);
        unsigned m2 = (unsigned)ej % (unsigned)(ei + 1);
        unsigned g  = m1 < m2 ? m1 : m2;
        int mx = ei > ej ? ei : ej;
        bias = (float)g / (float)(mx + 1);
    }
    biasOut[idx] = bias;
}

// ---------------- tf32 mma GEMM: 128x128 block tile, 32 k-tile, 8 warps ----------------
#define BK 32
#define APAD 36
#define BPAD 132
#define AS_STAGE (128*APAD)    // floats
#define BS_STAGE (BK*BPAD)     // floats
#define GSMEM ((2*AS_STAGE + 2*BS_STAGE)*4)

__device__ __forceinline__ void cp16(float* dst, const float* src) {
    unsigned a = (unsigned)__cvta_generic_to_shared(dst);
    asm volatile("cp.async.cg.shared.global [%0], [%1], 16;\n" :: "r"(a), "l"(src));
}

__device__ __forceinline__ void load_stage(const float* __restrict__ A,
                                           const float* __restrict__ B, int K,
                                           int br, int bc, int k0,
                                           float* As, float* Bs, int tid)
{
    #pragma unroll
    for (int i = 0; i < 4; i++) {
        int f = tid + i*256;
        int r = f >> 3, c = (f & 7) << 2;
        cp16(&As[r*APAD + c], A + (size_t)(br + r)*K + k0 + c);
    }
    #pragma unroll
    for (int i = 0; i < 4; i++) {
        int f = tid + i*256;
        int r = f >> 5, c = (f & 31) << 2;
        cp16(&Bs[r*BPAD + c], B + (size_t)(k0 + r)*1024 + bc + c);
    }
    asm volatile("cp.async.commit_group;\n");
}

__device__ __forceinline__ void compute_stage(const float* __restrict__ As,
                                              const float* __restrict__ Bs,
                                              int warpM, int warpN, int lane,
                                              float acc[4][4][4])
{
    int lr = lane >> 2, lc = lane & 3;
    #pragma unroll
    for (int k8 = 0; k8 < BK; k8 += 8) {
        unsigned a[4][4], b[4][2];
        #pragma unroll
        for (int mt = 0; mt < 4; mt++) {
            const float* p = &As[(warpM*64 + mt*16 + lr)*APAD + k8 + lc];
            a[mt][0] = __float_as_uint(p[0]);
            a[mt][1] = __float_as_uint(p[8*APAD]);
            a[mt][2] = __float_as_uint(p[4]);
            a[mt][3] = __float_as_uint(p[8*APAD + 4]);
        }
        #pragma unroll
        for (int nt = 0; nt < 4; nt++) {
            const float* p = &Bs[(k8 + lc)*BPAD + warpN*32 + nt*8 + lr];
            b[nt][0] = __float_as_uint(p[0]);
            b[nt][1] = __float_as_uint(p[4*BPAD]);
        }
        #pragma unroll
        for (int mt = 0; mt < 4; mt++)
            #pragma unroll
            for (int nt = 0; nt < 4; nt++)
                asm volatile(
                    "mma.sync.aligned.m16n8k8.row.col.f32.tf32.tf32.f32 "
                    "{%0,%1,%2,%3}, {%4,%5,%6,%7}, {%8,%9}, {%0,%1,%2,%3};"
                    : "+f"(acc[mt][nt][0]), "+f"(acc[mt][nt][1]),
                      "+f"(acc[mt][nt][2]), "+f"(acc[mt][nt][3])
                    : "r"(a[mt][0]), "r"(a[mt][1]), "r"(a[mt][2]), "r"(a[mt][3]),
                      "r"(b[nt][0]), "r"(b[nt][1]));
    }
}

__device__ __forceinline__ void mma_gemm(const float* __restrict__ A,
                                         const float* __restrict__ B, int K,
                                         int br, int bc, int tid, float* sm,
                                         float acc[4][4][4])
{
    float* As0 = sm;
    float* As1 = sm + AS_STAGE;
    float* Bs0 = sm + 2*AS_STAGE;
    float* Bs1 = sm + 2*AS_STAGE + BS_STAGE;
    int warp = tid >> 5, lane = tid & 31;
    int warpM = warp >> 2, warpN = warp & 3;
    int KT = K / BK;
    load_stage(A, B, K, br, bc, 0, As0, Bs0, tid);
    for (int kt = 0; kt < KT; kt++) {
        float* Asc = (kt & 1) ? As1 : As0;
        float* Bsc = (kt & 1) ? Bs1 : Bs0;
        if (kt + 1 < KT) {
            float* Asn = ((kt+1) & 1) ? As1 : As0;
            float* Bsn = ((kt+1) & 1) ? Bs1 : Bs0;
            load_stage(A, B, K, br, bc, (kt+1)*BK, Asn, Bsn, tid);
            asm volatile("cp.async.wait_group 1;\n");
        } else {
            asm volatile("cp.async.wait_group 0;\n");
        }
        __syncthreads();
        compute_stage(Asc, Bsc, warpM, warpN, lane, acc);
        __syncthreads();
    }
}

__device__ __forceinline__ void mma_epi(float* __restrict__ C,
                                        const float* __restrict__ b1,
                                        const float* __restrict__ b2,
                                        int br, int bc, int tid,
                                        float acc[4][4][4], bool round_out)
{
    int warp = tid >> 5, lane = tid & 31;
    int warpM = warp >> 2, warpN = warp & 3;
    int lr = lane >> 2, lc = lane & 3;
    #pragma unroll
    for (int mt = 0; mt < 4; mt++)
        #pragma unroll
        for (int nt = 0; nt < 4; nt++) {
            int row = br + warpM*64 + mt*16 + lr;
            int col = bc + warpN*32 + nt*8 + lc*2;
            float bb0 = b1[col]   + b2[col];
            float bb1 = b1[col+1] + b2[col+1];
            float2 v0, v1;
            v0.x = acc[mt][nt][0] + bb0;
            v0.y = acc[mt][nt][1] + bb1;
            v1.x = acc[mt][nt][2] + bb0;
            v1.y = acc[mt][nt][3] + bb1;
            if (round_out) {
                v0.x = tf32r(v0.x); v0.y = tf32r(v0.y);
                v1.x = tf32r(v1.x); v1.y = tf32r(v1.y);
            }
            *(float2*)(C + (size_t)row*1024 + col) = v0;
            *(float2*)(C + (size_t)(row+8)*1024 + col) = v1;
        }
}

extern __shared__ float dsm[];

// hidden = featA @ emb2 + featF @ fus + biases, rounded to tf32
__global__ void __launch_bounds__(256) gemm_hidden_t(
        const float* __restrict__ A1, const float* __restrict__ B1,
        const float* __restrict__ A2, const float* __restrict__ B2,
        const float* __restrict__ bias1, const float* __restrict__ bias2,
        float* __restrict__ C)
{
    float acc[4][4][4];
    #pragma unroll
    for (int i = 0; i < 4; i++)
        #pragma unroll
        for (int j = 0; j < 4; j++)
            #pragma unroll
            for (int k = 0; k < 4; k++) acc[i][j][k] = 0.0f;
    int br = blockIdx.y * 128, bc = blockIdx.x * 128;
    mma_gemm(A1, B1, 512,  br, bc, threadIdx.x, dsm, acc);
    mma_gemm(A2, B2, 1024, br, bc, threadIdx.x, dsm, acc);
    mma_epi(C, bias1, bias2, br, bc, threadIdx.x, acc, true);
}

__global__ void __launch_bounds__(256) gemm_qkv_t(
        const float* __restrict__ Hd,
        const float* __restrict__ q_w, const float* __restrict__ q_b,
        const float* __restrict__ k_w, const float* __restrict__ k_b,
        const float* __restrict__ v_w, const float* __restrict__ v_b,
        const float* __restrict__ zero_b,
        float* __restrict__ Qo, float* __restrict__ Ko, float* __restrict__ Vo)
{
    const float* W; const float* bb; float* C;
    if (blockIdx.z == 0)      { W = q_w; bb = q_b; C = Qo; }
    else if (blockIdx.z == 1) { W = k_w; bb = k_b; C = Ko; }
    else                      { W = v_w; bb = v_b; C = Vo; }
    float acc[4][4][4];
    #pragma unroll
    for (int i = 0; i < 4; i++)
        #pragma unroll
        for (int j = 0; j < 4; j++)
            #pragma unroll
            for (int k = 0; k < 4; k++) acc[i][j][k] = 0.0f;
    int br = blockIdx.y * 128, bc = blockIdx.x * 128;
    mma_gemm(Hd, W, 1024, br, bc, threadIdx.x, dsm, acc);
    mma_epi(C, bb, zero_b, br, bc, threadIdx.x, acc, false);
}

__global__ void __launch_bounds__(256) gemm_single_t(
        const float* __restrict__ A, const float* __restrict__ W,
        const float* __restrict__ bias, const float* __restrict__ zero_b,
        float* __restrict__ C)
{
    float acc[4][4][4];
    #pragma unroll
    for (int i = 0; i < 4; i++)
        #pragma unroll
        for (int j = 0; j < 4; j++)
            #pragma unroll
            for (int k = 0; k < 4; k++) acc[i][j][k] = 0.0f;
    int br = blockIdx.y * 128, bc = blockIdx.x * 128;
    mma_gemm(A, W, 1024, br, bc, threadIdx.x, dsm, acc);
    mma_epi(C, bias, zero_b, br, bc, threadIdx.x, acc, false);
}

// ---------------- flash attention: 64x64 tiles, fp32 ----------------
#define QPAD 68
#define ATTN_SMEM (4 * 64 * QPAD * 4)

__global__ void __launch_bounds__(256) attention_kernel(
        const float* __restrict__ q, const float* __restrict__ k, const float* __restrict__ v,
        const float* __restrict__ biasG, const float* __restrict__ arith_bias,
        const float* __restrict__ gcd_w, float* __restrict__ o)
{
    extern __shared__ float sm[];
    float* sQ = sm;
    float* sK = sm + 64 * QPAD;
    float* sV = sm + 2 * 64 * QPAD;
    float* sP = sm + 3 * 64 * QPAD;

    int bh = blockIdx.y;
    int b = bh >> 4;
    int h = bh & 15;
    int i0 = blockIdx.x * 64;
    int tid = threadIdx.x;
    int tx = tid & 15, ty = tid >> 4;
    float gw = gcd_w[0];
    float ab = arith_bias[h];
    const float scale = 0.125f;
    const float* biasB = biasG + b * (Sz * Sz);

    for (int f = tid; f < 64 * 16; f += 256) {
        int r = f >> 4, c4 = (f & 15) * 4;
        *(float4*)(&sQ[r * QPAD + c4]) =
            *(const float4*)(q + ((b*Sz + i0 + r) * Dm) + h*HD + c4);
    }

    float m_i[4], l_i[4], acc[4][4];
    #pragma unroll
    for (int r = 0; r < 4; r++) {
        m_i[r] = -1e30f; l_i[r] = 0.0f;
        #pragma unroll
        for (int c = 0; c < 4; c++) acc[r][c] = 0.0f;
    }

    for (int j0 = 0; j0 < Sz; j0 += 64) {
        __syncthreads();
        for (int f = tid; f < 64 * 16; f += 256) {
            int r = f >> 4, c4 = (f & 15) * 4;
            int base = ((b*Sz + j0 + r) * Dm) + h*HD + c4;
            *(float4*)(&sK[r * QPAD + c4]) = *(const float4*)(k + base);
            *(float4*)(&sV[r * QPAD + c4]) = *(const float4*)(v + base);
        }
        __syncthreads();

        float s[4][4];
        #pragma unroll
        for (int r = 0; r < 4; r++)
            #pragma unroll
            for (int c = 0; c < 4; c++) s[r][c] = 0.0f;
        #pragma unroll 4
        for (int d = 0; d < 64; d++) {
            float a_[4], b_[4];
            #pragma unroll
            for (int r = 0; r < 4; r++) a_[r] = sQ[(ty*4 + r) * QPAD + d];
            #pragma unroll
            for (int c = 0; c < 4; c++) b_[c] = sK[(tx*4 + c) * QPAD + d];
            #pragma unroll
            for (int r = 0; r < 4; r++)
                #pragma unroll
                for (int c = 0; c < 4; c++)
                    s[r][c] = fmaf(a_[r], b_[c], s[r][c]);
        }

        #pragma unroll
        for (int r = 0; r < 4; r++) {
            int gi = i0 + ty*4 + r;
            float4 bb = *(const float4*)(biasB + gi * Sz + j0 + tx*4);
            s[r][0] = fmaf(bb.x, gw, s[r][0] * scale + ab);
            s[r][1] = fmaf(bb.y, gw, s[r][1] * scale + ab);
            s[r][2] = fmaf(bb.z, gw, s[r][2] * scale + ab);
            s[r][3] = fmaf(bb.w, gw, s[r][3] * scale + ab);

            float pm = fmaxf(fmaxf(s[r][0], s[r][1]), fmaxf(s[r][2], s[r][3]));
            #pragma unroll
            for (int ofs = 8; ofs >= 1; ofs >>= 1)
                pm = fmaxf(pm, __shfl_xor_sync(0xffffffffu, pm, ofs));
            float mnew = fmaxf(m_i[r], pm);
            float corr = __expf(m_i[r] - mnew);
            float psum = 0.0f;
            #pragma unroll
            for (int c = 0; c < 4; c++) {
                s[r][c] = __expf(s[r][c] - mnew);
                psum += s[r][c];
            }
            #pragma unroll
            for (int ofs = 8; ofs >= 1; ofs >>= 1)
                psum += __shfl_xor_sync(0xffffffffu, psum, ofs);
            l_i[r] = l_i[r] * corr + psum;
            m_i[r] = mnew;
            #pragma unroll
            for (int c = 0; c < 4; c++) acc[r][c] *= corr;
            *(float4*)(&sP[(ty*4 + r) * QPAD + tx*4]) =
                make_float4(s[r][0], s[r][1], s[r][2], s[r][3]);
        }
        __syncthreads();

        #pragma unroll 4
        for (int jj = 0; jj < 64; jj++) {
            float pv[4], vv[4];
            #pragma unroll
            for (int r = 0; r < 4; r++) pv[r] = sP[(ty*4 + r) * QPAD + jj];
            #pragma unroll
            for (int c = 0; c < 4; c++) vv[c] = sV[jj * QPAD + tx*4 + c];
            #pragma unroll
            for (int r = 0; r < 4; r++)
                #pragma unroll
                for (int c = 0; c < 4; c++)
                    acc[r][c] = fmaf(pv[r], vv[c], acc[r][c]);
        }
    }

    // epilogue: normalize, round to tf32 (feeds O-proj tf32 GEMM), write
    #pragma unroll
    for (int r = 0; r < 4; r++) {
        float inv = 1.0f / l_i[r];
        int gi = i0 + ty*4 + r;
        float4 ov = make_float4(tf32r(acc[r][0]*inv), tf32r(acc[r][1]*inv),
                                tf32r(acc[r][2]*inv), tf32r(acc[r][3]*inv));
        *(float4*)(o + ((b*Sz + gi) * Dm) + h*HD + tx*4) = ov;
    }
}

// ---------------- launch ----------------
extern "C" void kernel_launch(void* const* d_in, const int* in_sizes, int n_in,
                              void* d_out, int out_size)
{
    int enc_idx = -1;
    for (int i = 0; i < n_in; i++) if (in_sizes[i] == 4096) { enc_idx = i; break; }
    if (enc_idx < 0) enc_idx = 0;

    const float* P[24];
    int p = 0;
    for (int i = 0; i < n_in && p < 24; i++) {
        if (i == enc_idx) continue;
        P[p++] = (const float*)d_in[i];
    }
    const int* enc = (const int*)d_in[enc_idx];
    const float *q_w = P[0],  *q_b = P[1],  *k_w = P[2],  *k_b = P[3];
    const float *v_w = P[4],  *v_b = P[5],  *o_w = P[6],  *o_b = P[7];
    const float *emb1_w = P[8],  *emb1_b = P[9],  *emb2_w = P[10], *emb2_b = P[11];
    const float *log_w = P[12],  *log_b = P[13],  *prime_w = P[14], *prime_b = P[15];
    const float *div_w = P[16],  *div_b = P[17],  *bit_w = P[18],  *bit_b = P[19];
    const float *fus_w = P[20],  *fus_b = P[21],  *arith = P[22],  *gcdw = P[23];
    float* out = (float*)d_out;

    float *featA, *featF, *hidden, *Q, *K, *V, *attn, *biasM, *zb;
    float *qwT, *kwT, *vwT, *owT, *emb2T, *fusT;
    cudaGetSymbolAddress((void**)&featA,  g_featA);
    cudaGetSymbolAddress((void**)&featF,  g_featF);
    cudaGetSymbolAddress((void**)&hidden, g_hidden);
    cudaGetSymbolAddress((void**)&Q,      g_q);
    cudaGetSymbolAddress((void**)&K,      g_k);
    cudaGetSymbolAddress((void**)&V,      g_v);
    cudaGetSymbolAddress((void**)&attn,   g_attn);
    cudaGetSymbolAddress((void**)&biasM,  g_bias);
    cudaGetSymbolAddress((void**)&zb,     g_zero_bias);
    cudaGetSymbolAddress((void**)&qwT,    g_qw_t);
    cudaGetSymbolAddress((void**)&kwT,    g_kw_t);
    cudaGetSymbolAddress((void**)&vwT,    g_vw_t);
    cudaGetSymbolAddress((void**)&owT,    g_ow_t);
    cudaGetSymbolAddress((void**)&emb2T,  g_emb2_t);
    cudaGetSymbolAddress((void**)&fusT,   g_fus_t);

    cudaFuncSetAttribute(gemm_hidden_t, cudaFuncAttributeMaxDynamicSharedMemorySize, GSMEM);
    cudaFuncSetAttribute(gemm_qkv_t,    cudaFuncAttributeMaxDynamicSharedMemorySize, GSMEM);
    cudaFuncSetAttribute(gemm_single_t, cudaFuncAttributeMaxDynamicSharedMemorySize, GSMEM);
    cudaFuncSetAttribute(attention_kernel, cudaFuncAttributeMaxDynamicSharedMemorySize, ATTN_SMEM);

    // weight conversion to tf32
    convert_tf32_kernel<<<4096, 256>>>(q_w,    qwT,   1024*1024);
    convert_tf32_kernel<<<4096, 256>>>(k_w,    kwT,   1024*1024);
    convert_tf32_kernel<<<4096, 256>>>(v_w,    vwT,   1024*1024);
    convert_tf32_kernel<<<4096, 256>>>(o_w,    owT,   1024*1024);
    convert_tf32_kernel<<<2048, 256>>>(emb2_w, emb2T, 512*1024);
    convert_tf32_kernel<<<4096, 256>>>(fus_w,  fusT,  1024*1024);

    featurize_kernel<<<NT, 256>>>(enc, emb1_w, emb1_b, log_w, log_b,
                                  prime_w, prime_b, div_w, div_b, bit_w, bit_b,
                                  featA, featF);
    bias_kernel<<<(Bz*Sz*Sz + 255) / 256, 256>>>(enc, biasM);

    gemm_hidden_t<<<dim3(8, 32), 256, GSMEM>>>(featA, emb2T, featF, fusT,
                                               emb2_b, fus_b, hidden);
    gemm_qkv_t<<<dim3(8, 32, 3), 256, GSMEM>>>(hidden, qwT, q_b, kwT, k_b, vwT, v_b,
                                               zb, Q, K, V);
    attention_kernel<<<dim3(Sz/64, Bz*Hh), 256, ATTN_SMEM>>>(Q, K, V, biasM,
                                                             arith, gcdw, attn);
    gemm_single_t<<<dim3(8, 32), 256, GSMEM>>>(attn, owT, o_b, zb, out);
}

// round 5
// speedup vs baseline: 2.5733x; 1.8029x over previous
#include <cuda_runtime.h>
#include <cuda_bf16.h>
#include <math.h>

#define Bz 2
#define Sz 2048
#define Dm 1024
#define Hh 16
#define HD 64
#define NT (Bz*Sz)          // 4096 tokens

// ---------------- scratch (device globals) ----------------
__device__ float g_featA[NT * 512];
__device__ float g_featF[NT * 1024];
__device__ float g_hidden[NT * 1024];
__device__ float g_q[NT * 1024];
__device__ float g_k[NT * 1024];
__device__ float g_v[NT * 1024];
__device__ float g_attn[NT * 1024];
__device__ float g_bias[Bz * Sz * Sz];     // 33.5 MB
__device__ float g_zero_bias[1024];        // stays zero
// tf32-rounded weight copies
__device__ float g_qw_t[1024*1024];
__device__ float g_kw_t[1024*1024];
__device__ float g_vw_t[1024*1024];
__device__ float g_ow_t[1024*1024];
__device__ float g_emb2_t[512*1024];
__device__ float g_fus_t[1024*1024];

// ---------------- tf32 rounding ----------------
__device__ __forceinline__ float tf32r(float x) {
    unsigned r;
    asm("cvt.rna.tf32.f32 %0, %1;" : "=r"(r) : "f"(x));
    return __uint_as_float(r);
}

__global__ void convert_tf32_kernel(const float* __restrict__ s, float* __restrict__ d, int n) {
    int i = blockIdx.x * 256 + threadIdx.x;
    if (i < n) d[i] = tf32r(s[i]);
}

// ---------------- mma helper ----------------
__device__ __forceinline__ void mma_tf32(float* acc, const unsigned* a, unsigned b0, unsigned b1) {
    asm volatile(
        "mma.sync.aligned.m16n8k8.row.col.f32.tf32.tf32.f32 "
        "{%0,%1,%2,%3}, {%4,%5,%6,%7}, {%8,%9}, {%0,%1,%2,%3};"
        : "+f"(acc[0]), "+f"(acc[1]), "+f"(acc[2]), "+f"(acc[3])
        : "r"(a[0]), "r"(a[1]), "r"(a[2]), "r"(a[3]), "r"(b0), "r"(b1));
}

// ---------------- featurize ----------------
__global__ void featurize_kernel(const int* __restrict__ enc,
                                 const float* __restrict__ emb1_w, const float* __restrict__ emb1_b,
                                 const float* __restrict__ log_w,  const float* __restrict__ log_b,
                                 const float* __restrict__ prime_w,const float* __restrict__ prime_b,
                                 const float* __restrict__ div_w,  const float* __restrict__ div_b,
                                 const float* __restrict__ bit_w,  const float* __restrict__ bit_b,
                                 float* __restrict__ featA, float* __restrict__ featF)
{
    int t = blockIdx.x;
    int tid = threadIdx.x;
    int e = enc[t];
    float ef = (float)e;
    float norm = ef / 2147483647.0f;
    float lg = logf(ef + 1.0f);

    __shared__ float pflag[10];
    __shared__ float dfrac[20];
    __shared__ float bflag[32];
    if (tid < 10) {
        const int primes[10] = {2,3,5,7,11,13,17,19,23,29};
        pflag[tid] = (e % primes[tid] == 0) ? 1.0f : 0.0f;
    } else if (tid < 30) {
        int tv = (tid - 10) + 2;
        dfrac[tid-10] = (float)(e % tv) / (float)tv;
    } else if (tid < 62) {
        int s = tid - 30;
        bflag[s] = (float)((e >> s) & 1);
    }
    __syncthreads();

    for (int c = tid; c < 512; c += 256) {
        float vv = fmaf(norm, emb1_w[c], emb1_b[c]);
        featA[t*512 + c] = tf32r(fmaxf(vv, 0.0f));
    }
    for (int c = tid; c < 1024; c += 256) {
        int cc = c & 255;
        float vv;
        if (c < 256) {
            vv = fmaf(lg, log_w[cc], log_b[cc]);
        } else if (c < 512) {
            vv = prime_b[cc];
            #pragma unroll
            for (int p = 0; p < 10; p++) vv = fmaf(pflag[p], prime_w[p*256 + cc], vv);
        } else if (c < 768) {
            vv = div_b[cc];
            #pragma unroll
            for (int p = 0; p < 20; p++) vv = fmaf(dfrac[p], div_w[p*256 + cc], vv);
        } else {
            vv = bit_b[cc];
            #pragma unroll
            for (int p = 0; p < 32; p++) vv = fmaf(bflag[p], bit_w[p*256 + cc], vv);
        }
        featF[t*1024 + c] = tf32r(vv);
    }
}

// ---------------- pairwise gcd-approx bias precompute ----------------
__global__ void bias_kernel(const int* __restrict__ enc, float* __restrict__ biasOut)
{
    int idx = blockIdx.x * blockDim.x + threadIdx.x;
    if (idx >= Bz*Sz*Sz) return;
    int j = idx & (Sz - 1);
    int r = idx >> 11;
    int i = r & (Sz - 1);
    int b = r >> 11;
    int ei = enc[b*Sz + i];
    int ej = enc[b*Sz + j];
    float bias;
    if (i == j) {
        bias = 0.0f;
    } else {
        unsigned m1 = (unsigned)ei % (unsigned)(ej + 1);
        unsigned m2 = (unsigned)ej % (unsigned)(ei + 1);
        unsigned g  = m1 < m2 ? m1 : m2;
        int mx = ei > ej ? ei : ej;
        bias = (float)g / (float)(mx + 1);
    }
    biasOut[idx] = bias;
}

// ---------------- tf32 mma GEMM: 128x128 block tile, 32 k-tile, 8 warps ----------------
#define BK 32
#define APAD 36
#define BPAD 132
#define AS_STAGE (128*APAD)
#define BS_STAGE (BK*BPAD)
#define GSMEM ((2*AS_STAGE + 2*BS_STAGE)*4)

__device__ __forceinline__ void cp16(float* dst, const float* src) {
    unsigned a = (unsigned)__cvta_generic_to_shared(dst);
    asm volatile("cp.async.cg.shared.global [%0], [%1], 16;\n" :: "r"(a), "l"(src));
}

__device__ __forceinline__ void load_stage(const float* __restrict__ A,
                                           const float* __restrict__ B, int K,
                                           int br, int bc, int k0,
                                           float* As, float* Bs, int tid)
{
    #pragma unroll
    for (int i = 0; i < 4; i++) {
        int f = tid + i*256;
        int r = f >> 3, c = (f & 7) << 2;
        cp16(&As[r*APAD + c], A + (size_t)(br + r)*K + k0 + c);
    }
    #pragma unroll
    for (int i = 0; i < 4; i++) {
        int f = tid + i*256;
        int r = f >> 5, c = (f & 31) << 2;
        cp16(&Bs[r*BPAD + c], B + (size_t)(k0 + r)*1024 + bc + c);
    }
    asm volatile("cp.async.commit_group;\n");
}

__device__ __forceinline__ void compute_stage(const float* __restrict__ As,
                                              const float* __restrict__ Bs,
                                              int warpM, int warpN, int lane,
                                              float acc[4][4][4])
{
    int lr = lane >> 2, lc = lane & 3;
    #pragma unroll
    for (int k8 = 0; k8 < BK; k8 += 8) {
        unsigned a[4][4], b[4][2];
        #pragma unroll
        for (int mt = 0; mt < 4; mt++) {
            const float* p = &As[(warpM*64 + mt*16 + lr)*APAD + k8 + lc];
            a[mt][0] = __float_as_uint(p[0]);
            a[mt][1] = __float_as_uint(p[8*APAD]);
            a[mt][2] = __float_as_uint(p[4]);
            a[mt][3] = __float_as_uint(p[8*APAD + 4]);
        }
        #pragma unroll
        for (int nt = 0; nt < 4; nt++) {
            const float* p = &Bs[(k8 + lc)*BPAD + warpN*32 + nt*8 + lr];
            b[nt][0] = __float_as_uint(p[0]);
            b[nt][1] = __float_as_uint(p[4*BPAD]);
        }
        #pragma unroll
        for (int mt = 0; mt < 4; mt++)
            #pragma unroll
            for (int nt = 0; nt < 4; nt++)
                mma_tf32(acc[mt][nt], a[mt], b[nt][0], b[nt][1]);
    }
}

__device__ __forceinline__ void mma_gemm(const float* __restrict__ A,
                                         const float* __restrict__ B, int K,
                                         int br, int bc, int tid, float* sm,
                                         float acc[4][4][4])
{
    float* As0 = sm;
    float* As1 = sm + AS_STAGE;
    float* Bs0 = sm + 2*AS_STAGE;
    float* Bs1 = sm + 2*AS_STAGE + BS_STAGE;
    int warp = tid >> 5, lane = tid & 31;
    int warpM = warp >> 2, warpN = warp & 3;
    int KT = K / BK;
    load_stage(A, B, K, br, bc, 0, As0, Bs0, tid);
    for (int kt = 0; kt < KT; kt++) {
        float* Asc = (kt & 1) ? As1 : As0;
        float* Bsc = (kt & 1) ? Bs1 : Bs0;
        if (kt + 1 < KT) {
            float* Asn = ((kt+1) & 1) ? As1 : As0;
            float* Bsn = ((kt+1) & 1) ? Bs1 : Bs0;
            load_stage(A, B, K, br, bc, (kt+1)*BK, Asn, Bsn, tid);
            asm volatile("cp.async.wait_group 1;\n");
        } else {
            asm volatile("cp.async.wait_group 0;\n");
        }
        __syncthreads();
        compute_stage(Asc, Bsc, warpM, warpN, lane, acc);
        __syncthreads();
    }
}

__device__ __forceinline__ void mma_epi(float* __restrict__ C,
                                        const float* __restrict__ b1,
                                        const float* __restrict__ b2,
                                        int br, int bc, int tid,
                                        float acc[4][4][4], bool round_out)
{
    int warp = tid >> 5, lane = tid & 31;
    int warpM = warp >> 2, warpN = warp & 3;
    int lr = lane >> 2, lc = lane & 3;
    #pragma unroll
    for (int mt = 0; mt < 4; mt++)
        #pragma unroll
        for (int nt = 0; nt < 4; nt++) {
            int row = br + warpM*64 + mt*16 + lr;
            int col = bc + warpN*32 + nt*8 + lc*2;
            float bb0 = b1[col]   + b2[col];
            float bb1 = b1[col+1] + b2[col+1];
            float2 v0, v1;
            v0.x = acc[mt][nt][0] + bb0;
            v0.y = acc[mt][nt][1] + bb1;
            v1.x = acc[mt][nt][2] + bb0;
            v1.y = acc[mt][nt][3] + bb1;
            if (round_out) {
                v0.x = tf32r(v0.x); v0.y = tf32r(v0.y);
                v1.x = tf32r(v1.x); v1.y = tf32r(v1.y);
            }
            *(float2*)(C + (size_t)row*1024 + col) = v0;
            *(float2*)(C + (size_t)(row+8)*1024 + col) = v1;
        }
}

extern __shared__ float dsm[];

__global__ void __launch_bounds__(256) gemm_hidden_t(
        const float* __restrict__ A1, const float* __restrict__ B1,
        const float* __restrict__ A2, const float* __restrict__ B2,
        const float* __restrict__ bias1, const float* __restrict__ bias2,
        float* __restrict__ C)
{
    float acc[4][4][4];
    #pragma unroll
    for (int i = 0; i < 4; i++)
        #pragma unroll
        for (int j = 0; j < 4; j++)
            #pragma unroll
            for (int k = 0; k < 4; k++) acc[i][j][k] = 0.0f;
    int br = blockIdx.y * 128, bc = blockIdx.x * 128;
    mma_gemm(A1, B1, 512,  br, bc, threadIdx.x, dsm, acc);
    mma_gemm(A2, B2, 1024, br, bc, threadIdx.x, dsm, acc);
    mma_epi(C, bias1, bias2, br, bc, threadIdx.x, acc, true);
}

__global__ void __launch_bounds__(256) gemm_qkv_t(
        const float* __restrict__ Hd,
        const float* __restrict__ q_w, const float* __restrict__ q_b,
        const float* __restrict__ k_w, const float* __restrict__ k_b,
        const float* __restrict__ v_w, const float* __restrict__ v_b,
        const float* __restrict__ zero_b,
        float* __restrict__ Qo, float* __restrict__ Ko, float* __restrict__ Vo)
{
    const float* W; const float* bb; float* C;
    if (blockIdx.z == 0)      { W = q_w; bb = q_b; C = Qo; }
    else if (blockIdx.z == 1) { W = k_w; bb = k_b; C = Ko; }
    else                      { W = v_w; bb = v_b; C = Vo; }
    float acc[4][4][4];
    #pragma unroll
    for (int i = 0; i < 4; i++)
        #pragma unroll
        for (int j = 0; j < 4; j++)
            #pragma unroll
            for (int k = 0; k < 4; k++) acc[i][j][k] = 0.0f;
    int br = blockIdx.y * 128, bc = blockIdx.x * 128;
    mma_gemm(Hd, W, 1024, br, bc, threadIdx.x, dsm, acc);
    mma_epi(C, bb, zero_b, br, bc, threadIdx.x, acc, false);
}

__global__ void __launch_bounds__(256) gemm_single_t(
        const float* __restrict__ A, const float* __restrict__ W,
        const float* __restrict__ bias, const float* __restrict__ zero_b,
        float* __restrict__ C)
{
    float acc[4][4][4];
    #pragma unroll
    for (int i = 0; i < 4; i++)
        #pragma unroll
        for (int j = 0; j < 4; j++)
            #pragma unroll
            for (int k = 0; k < 4; k++) acc[i][j][k] = 0.0f;
    int br = blockIdx.y * 128, bc = blockIdx.x * 128;
    mma_gemm(A, W, 1024, br, bc, threadIdx.x, dsm, acc);
    mma_epi(C, bias, zero_b, br, bc, threadIdx.x, acc, false);
}

// ---------------- tensor-core flash attention ----------------
// 64 q-rows per block (4 warps x 16), 64-key tiles, tf32 mma.
// QK^T: 3-mma error-compensated split (~fp32 accurate scores).
// P@V: single-pass tf32.
#define KPAD 68
#define VPAD 72
#define PPAD 68
#define ATTN_SMEM ((2*64*KPAD + 64*VPAD + 64*PPAD)*4)

__global__ void __launch_bounds__(128) attention_mma_kernel(
        const float* __restrict__ q, const float* __restrict__ k, const float* __restrict__ v,
        const float* __restrict__ biasG, const float* __restrict__ gcd_w,
        float* __restrict__ o)
{
    extern __shared__ float sm[];
    float* sKb = sm;
    float* sKs = sm + 64*KPAD;
    float* sV  = sm + 2*64*KPAD;
    float* sP  = sm + 2*64*KPAD + 64*VPAD;

    int bh = blockIdx.y;
    int b = bh >> 4, h = bh & 15;
    int i0 = blockIdx.x * 64;
    int tid = threadIdx.x;
    int w = tid >> 5, lane = tid & 31;
    int lr = lane >> 2, lc = lane & 3;
    float gw = gcd_w[0];
    const float scale = 0.125f;                // 1/sqrt(64)
    const float* biasB = biasG + (size_t)b * Sz * Sz;

    // ---- Q fragments in registers (split big/small), loop-invariant ----
    unsigned Qb[8][4], Qs[8][4];
    {
        int r0 = i0 + w*16 + lr;
        const float* qbase = q + (size_t)(b*Sz)*Dm + h*HD;
        #pragma unroll
        for (int k8 = 0; k8 < 8; k8++) {
            #pragma unroll
            for (int i = 0; i < 4; i++) {
                int rr = r0 + (i & 1)*8;
                int cc = k8*8 + lc + (i >> 1)*4;
                float qv = qbase[(size_t)rr*Dm + cc];
                float qbig = tf32r(qv);
                Qb[k8][i] = __float_as_uint(qbig);
                Qs[k8][i] = __float_as_uint(tf32r(qv - qbig));
            }
        }
    }

    float m0 = -1e30f, m1 = -1e30f, l0 = 0.0f, l1 = 0.0f;
    float acc[8][4];
    #pragma unroll
    for (int nt = 0; nt < 8; nt++)
        #pragma unroll
        for (int i = 0; i < 4; i++) acc[nt][i] = 0.0f;

    int gi0 = i0 + w*16 + lr;

    for (int j0 = 0; j0 < Sz; j0 += 64) {
        __syncthreads();
        // ---- load K (split) and V tiles ----
        for (int f = tid; f < 64*16; f += 128) {
            int r = f >> 4, c4 = (f & 15) * 4;
            size_t base = (size_t)(b*Sz + j0 + r) * Dm + h*HD + c4;
            float4 kv = *(const float4*)(k + base);
            float4 kb, ks;
            kb.x = tf32r(kv.x); ks.x = tf32r(kv.x - kb.x);
            kb.y = tf32r(kv.y); ks.y = tf32r(kv.y - kb.y);
            kb.z = tf32r(kv.z); ks.z = tf32r(kv.z - kb.z);
            kb.w = tf32r(kv.w); ks.w = tf32r(kv.w - kb.w);
            *(float4*)(&sKb[r*KPAD + c4]) = kb;
            *(float4*)(&sKs[r*KPAD + c4]) = ks;
            float4 vv = *(const float4*)(v + base);
            vv.x = tf32r(vv.x); vv.y = tf32r(vv.y);
            vv.z = tf32r(vv.z); vv.w = tf32r(vv.w);
            *(float4*)(&sV[r*VPAD + c4]) = vv;
        }
        __syncthreads();

        // ---- S = Q K^T (3-mma split) ----
        float s[8][4];
        #pragma unroll
        for (int nt = 0; nt < 8; nt++)
            #pragma unroll
            for (int i = 0; i < 4; i++) s[nt][i] = 0.0f;

        #pragma unroll
        for (int k8 = 0; k8 < 8; k8++) {
            #pragma unroll
            for (int nt = 0; nt < 8; nt++) {
                int bo = (nt*8 + lr)*KPAD + k8*8 + lc;
                unsigned kb0 = __float_as_uint(sKb[bo]);
                unsigned kb1 = __float_as_uint(sKb[bo + 4]);
                unsigned ks0 = __float_as_uint(sKs[bo]);
                unsigned ks1 = __float_as_uint(sKs[bo + 4]);
                mma_tf32(s[nt], Qb[k8], kb0, kb1);
                mma_tf32(s[nt], Qs[k8], kb0, kb1);
                mma_tf32(s[nt], Qb[k8], ks0, ks1);
            }
        }

        // ---- scale + gcd bias (arith_bias is per-head constant: softmax-invariant, dropped) ----
        #pragma unroll
        for (int nt = 0; nt < 8; nt++) {
            size_t cix = (size_t)gi0*Sz + j0 + nt*8 + 2*lc;
            float2 b0 = *(const float2*)(biasB + cix);
            float2 b1 = *(const float2*)(biasB + cix + 8*(size_t)Sz);
            s[nt][0] = fmaf(b0.x, gw, s[nt][0]*scale);
            s[nt][1] = fmaf(b0.y, gw, s[nt][1]*scale);
            s[nt][2] = fmaf(b1.x, gw, s[nt][2]*scale);
            s[nt][3] = fmaf(b1.y, gw, s[nt][3]*scale);
        }

        // ---- online softmax (rows lr and lr+8; reduce over quad lanes) ----
        float tm0 = -1e30f, tm1 = -1e30f;
        #pragma unroll
        for (int nt = 0; nt < 8; nt++) {
            tm0 = fmaxf(tm0, fmaxf(s[nt][0], s[nt][1]));
            tm1 = fmaxf(tm1, fmaxf(s[nt][2], s[nt][3]));
        }
        tm0 = fmaxf(tm0, __shfl_xor_sync(0xffffffffu, tm0, 1));
        tm0 = fmaxf(tm0, __shfl_xor_sync(0xffffffffu, tm0, 2));
        tm1 = fmaxf(tm1, __shfl_xor_sync(0xffffffffu, tm1, 1));
        tm1 = fmaxf(tm1, __shfl_xor_sync(0xffffffffu, tm1, 2));
        float mn0 = fmaxf(m0, tm0), mn1 = fmaxf(m1, tm1);
        float c0 = __expf(m0 - mn0), c1 = __expf(m1 - mn1);
        float sum0 = 0.0f, sum1 = 0.0f;
        #pragma unroll
        for (int nt = 0; nt < 8; nt++) {
            s[nt][0] = __expf(s[nt][0] - mn0);
            s[nt][1] = __expf(s[nt][1] - mn0);
            s[nt][2] = __expf(s[nt][2] - mn1);
            s[nt][3] = __expf(s[nt][3] - mn1);
            sum0 += s[nt][0] + s[nt][1];
            sum1 += s[nt][2] + s[nt][3];
        }
        sum0 += __shfl_xor_sync(0xffffffffu, sum0, 1);
        sum0 += __shfl_xor_sync(0xffffffffu, sum0, 2);
        sum1 += __shfl_xor_sync(0xffffffffu, sum1, 1);
        sum1 += __shfl_xor_sync(0xffffffffu, sum1, 2);
        l0 = l0*c0 + sum0;  m0 = mn0;
        l1 = l1*c1 + sum1;  m1 = mn1;
        #pragma unroll
        for (int nt = 0; nt < 8; nt++) {
            acc[nt][0] *= c0; acc[nt][1] *= c0;
            acc[nt][2] *= c1; acc[nt][3] *= c1;
        }

        // ---- P to SMEM (warp-private region), reload as A-fragments ----
        #pragma unroll
        for (int nt = 0; nt < 8; nt++) {
            int po = (w*16 + lr)*PPAD + nt*8 + 2*lc;
            *(float2*)(&sP[po]) = make_float2(tf32r(s[nt][0]), tf32r(s[nt][1]));
            *(float2*)(&sP[po + 8*PPAD]) = make_float2(tf32r(s[nt][2]), tf32r(s[nt][3]));
        }
        __syncwarp();

        // ---- acc += P @ V ----
        #pragma unroll
        for (int k8 = 0; k8 < 8; k8++) {
            int ao = (w*16 + lr)*PPAD + k8*8 + lc;
            unsigned a[4];
            a[0] = __float_as_uint(sP[ao]);
            a[1] = __float_as_uint(sP[ao + 8*PPAD]);
            a[2] = __float_as_uint(sP[ao + 4]);
            a[3] = __float_as_uint(sP[ao + 8*PPAD + 4]);
            #pragma unroll
            for (int nt = 0; nt < 8; nt++) {
                int bo = (k8*8 + lc)*VPAD + nt*8 + lr;
                unsigned b0 = __float_as_uint(sV[bo]);
                unsigned b1 = __float_as_uint(sV[bo + 4*VPAD]);
                mma_tf32(acc[nt], a, b0, b1);
            }
        }
    }

    // ---- epilogue: normalize, round to tf32 for O-proj, write ----
    float inv0 = 1.0f / l0, inv1 = 1.0f / l1;
    #pragma unroll
    for (int nt = 0; nt < 8; nt++) {
        int col = h*HD + nt*8 + 2*lc;
        float2 o0 = make_float2(tf32r(acc[nt][0]*inv0), tf32r(acc[nt][1]*inv0));
        float2 o1 = make_float2(tf32r(acc[nt][2]*inv1), tf32r(acc[nt][3]*inv1));
        *(float2*)(o + (size_t)(b*Sz + gi0)*Dm + col) = o0;
        *(float2*)(o + (size_t)(b*Sz + gi0 + 8)*Dm + col) = o1;
    }
}

// ---------------- launch ----------------
extern "C" void kernel_launch(void* const* d_in, const int* in_sizes, int n_in,
                              void* d_out, int out_size)
{
    int enc_idx = -1;
    for (int i = 0; i < n_in; i++) if (in_sizes[i] == 4096) { enc_idx = i; break; }
    if (enc_idx < 0) enc_idx = 0;

    const float* P[24];
    int p = 0;
    for (int i = 0; i < n_in && p < 24; i++) {
        if (i == enc_idx) continue;
        P[p++] = (const float*)d_in[i];
    }
    const int* enc = (const int*)d_in[enc_idx];
    const float *q_w = P[0],  *q_b = P[1],  *k_w = P[2],  *k_b = P[3];
    const float *v_w = P[4],  *v_b = P[5],  *o_w = P[6],  *o_b = P[7];
    const float *emb1_w = P[8],  *emb1_b = P[9],  *emb2_w = P[10], *emb2_b = P[11];
    const float *log_w = P[12],  *log_b = P[13],  *prime_w = P[14], *prime_b = P[15];
    const float *div_w = P[16],  *div_b = P[17],  *bit_w = P[18],  *bit_b = P[19];
    const float *fus_w = P[20],  *fus_b = P[21],  *arith = P[22],  *gcdw = P[23];
    (void)arith;
    float* out = (float*)d_out;

    float *featA, *featF, *hidden, *Q, *K, *V, *attn, *biasM, *zb;
    float *qwT, *kwT, *vwT, *owT, *emb2T, *fusT;
    cudaGetSymbolAddress((void**)&featA,  g_featA);
    cudaGetSymbolAddress((void**)&featF,  g_featF);
    cudaGetSymbolAddress((void**)&hidden, g_hidden);
    cudaGetSymbolAddress((void**)&Q,      g_q);
    cudaGetSymbolAddress((void**)&K,      g_k);
    cudaGetSymbolAddress((void**)&V,      g_v);
    cudaGetSymbolAddress((void**)&attn,   g_attn);
    cudaGetSymbolAddress((void**)&biasM,  g_bias);
    cudaGetSymbolAddress((void**)&zb,     g_zero_bias);
    cudaGetSymbolAddress((void**)&qwT,    g_qw_t);
    cudaGetSymbolAddress((void**)&kwT,    g_kw_t);
    cudaGetSymbolAddress((void**)&vwT,    g_vw_t);
    cudaGetSymbolAddress((void**)&owT,    g_ow_t);
    cudaGetSymbolAddress((void**)&emb2T,  g_emb2_t);
    cudaGetSymbolAddress((void**)&fusT,   g_fus_t);

    cudaFuncSetAttribute(gemm_hidden_t, cudaFuncAttributeMaxDynamicSharedMemorySize, GSMEM);
    cudaFuncSetAttribute(gemm_qkv_t,    cudaFuncAttributeMaxDynamicSharedMemorySize, GSMEM);
    cudaFuncSetAttribute(gemm_single_t, cudaFuncAttributeMaxDynamicSharedMemorySize, GSMEM);
    cudaFuncSetAttribute(attention_mma_kernel, cudaFuncAttributeMaxDynamicSharedMemorySize, ATTN_SMEM);

    convert_tf32_kernel<<<4096, 256>>>(q_w,    qwT,   1024*1024);
    convert_tf32_kernel<<<4096, 256>>>(k_w,    kwT,   1024*1024);
    convert_tf32_kernel<<<4096, 256>>>(v_w,    vwT,   1024*1024);
    convert_tf32_kernel<<<4096, 256>>>(o_w,    owT,   1024*1024);
    convert_tf32_kernel<<<2048, 256>>>(emb2_w, emb2T, 512*1024);
    convert_tf32_kernel<<<4096, 256>>>(fus_w,  fusT,  1024*1024);

    featurize_kernel<<<NT, 256>>>(enc, emb1_w, emb1_b, log_w, log_b,
                                  prime_w, prime_b, div_w, div_b, bit_w, bit_b,
                                  featA, featF);
    bias_kernel<<<(Bz*Sz*Sz + 255) / 256, 256>>>(enc, biasM);

    gemm_hidden_t<<<dim3(8, 32), 256, GSMEM>>>(featA, emb2T, featF, fusT,
                                               emb2_b, fus_b, hidden);
    gemm_qkv_t<<<dim3(8, 32, 3), 256, GSMEM>>>(hidden, qwT, q_b, kwT, k_b, vwT, v_b,
                                               zb, Q, K, V);
    attention_mma_kernel<<<dim3(Sz/64, Bz*Hh), 128, ATTN_SMEM>>>(Q, K, V, biasM,
                                                                 gcdw, attn);
    gemm_single_t<<<dim3(8, 32), 256, GSMEM>>>(attn, owT, o_b, zb, out);
}